// round 2
// baseline (speedup 1.0000x reference)
#include <cuda_runtime.h>
#include <cstdint>

#define B_    16
#define C_    3
#define H_    512
#define W_    512
#define HW_   (H_ * W_)
#define NCLS  64
#define NSEG  (B_ * NCLS)

// 256-byte stride per bin: consecutive bins differ in address bit 8 (and up),
// which participates in the addr->LTS hash (bit 7 is transparent on sm_103a),
// spreading the 1024 hot atomic targets across ~all L2 slices.
#define STRIDE 32   /* u64 elements -> 256 B */
#define NBLK   1024

// Persistent accumulators, zero at module load; the last block restores them
// to zero every launch -> identical state on every graph replay.
__device__ unsigned long long d_bins[NSEG * STRIDE];
__device__ unsigned int       d_ticket;

// Packed fixed-point (one RED.ADD.64 carries count + sum):
//   bits [44:64) : pixel count  (max ~4.4k per bin << 2^20)
//   bits [ 0:44) : sum * 2^22   (max ~2e4 * 2^22 ~= 8.4e10 << 2^44)
#define SUM_SCALE     4194304.0f           /* 2^22 */
#define SUM_INV_SCALE (1.0f / 4194304.0f)
#define CNT_ONE       (1ull << 44)
#define SUM_MASK      ((1ull << 44) - 1ull)

__global__ void __launch_bounds__(256)
fused_kernel(const float* __restrict__ inp,
             const float* __restrict__ tgt,
             const int*   __restrict__ msk,
             float*       __restrict__ out)
{
    const int t        = threadIdx.x;
    const int b        = blockIdx.y;
    const int vec_base = blockIdx.x * 1024;     // 64 blocks per image, 1024 float4/block
    const int HW4      = HW_ / 4;

    const float4* ip = (const float4*)(inp + (size_t)b * C_ * HW_);
    const float4* tp = (const float4*)(tgt + (size_t)b * C_ * HW_);
    const int4*   mp = (const int4*)  (msk + (size_t)b * HW_);
    unsigned long long* bins_b = d_bins + (size_t)b * NCLS * STRIDE;

#pragma unroll
    for (int it = 0; it < 4; it++) {
        const int v = vec_base + it * 256 + t;

        const float4 a0 = __ldg(ip + v);
        const float4 a1 = __ldg(ip + HW4 + v);
        const float4 a2 = __ldg(ip + 2 * HW4 + v);
        const float4 c0 = __ldg(tp + v);
        const float4 c1 = __ldg(tp + HW4 + v);
        const float4 c2 = __ldg(tp + 2 * HW4 + v);
        const int4   m  = __ldg(mp + v);

        const float w0 = fabsf(a0.x - c0.x) + fabsf(a1.x - c1.x) + fabsf(a2.x - c2.x);
        const float w1 = fabsf(a0.y - c0.y) + fabsf(a1.y - c1.y) + fabsf(a2.y - c2.y);
        const float w2 = fabsf(a0.z - c0.z) + fabsf(a1.z - c1.z) + fabsf(a2.z - c2.z);
        const float w3 = fabsf(a0.w - c0.w) + fabsf(a1.w - c1.w) + fabsf(a2.w - c2.w);

        // atomicAdd with unused result -> ptxas emits RED (fire-and-forget),
        // integer add => bit-deterministic across replays.
        atomicAdd(&bins_b[(size_t)(m.x & (NCLS - 1)) * STRIDE],
                  CNT_ONE + __float2ull_rn(w0 * SUM_SCALE));
        atomicAdd(&bins_b[(size_t)(m.y & (NCLS - 1)) * STRIDE],
                  CNT_ONE + __float2ull_rn(w1 * SUM_SCALE));
        atomicAdd(&bins_b[(size_t)(m.z & (NCLS - 1)) * STRIDE],
                  CNT_ONE + __float2ull_rn(w2 * SUM_SCALE));
        atomicAdd(&bins_b[(size_t)(m.w & (NCLS - 1)) * STRIDE],
                  CNT_ONE + __float2ull_rn(w3 * SUM_SCALE));
    }

    // ---- last-block-done fusion of the finalize step ----
    __threadfence();                 // make this block's REDs visible
    __syncthreads();
    __shared__ unsigned int s_ticket;
    if (t == 0) s_ticket = atomicAdd(&d_ticket, 1u);
    __syncthreads();
    if (s_ticket != NBLK - 1) return;

    __threadfence();                 // acquire: all blocks' REDs now visible

    float tot = 0.0f, ws = 0.0f, mx = 0.0f;
    for (int i = t; i < NSEG; i += 256) {
        const unsigned long long p = d_bins[(size_t)i * STRIDE];
        d_bins[(size_t)i * STRIDE] = 0ull;          // reset for next replay
        const float        s = (float)(p & SUM_MASK) * SUM_INV_SCALE;
        const unsigned int c = (unsigned int)(p >> 44);
        const float avg = s / fmaxf((float)c * (float)C_, 1.0f);
        tot += s;
        ws  += s * avg;
        mx   = fmaxf(mx, avg);
    }

    // block reduction (256 threads)
#pragma unroll
    for (int o = 16; o > 0; o >>= 1) {
        tot += __shfl_xor_sync(0xffffffffu, tot, o);
        ws  += __shfl_xor_sync(0xffffffffu, ws,  o);
        mx   = fmaxf(mx, __shfl_xor_sync(0xffffffffu, mx, o));
    }
    __shared__ float stot[8], sws[8], smx[8];
    const int lane = t & 31, wid = t >> 5;
    if (lane == 0) { stot[wid] = tot; sws[wid] = ws; smx[wid] = mx; }
    __syncthreads();
    if (wid == 0) {
        tot = (lane < 8) ? stot[lane] : 0.0f;
        ws  = (lane < 8) ? sws[lane]  : 0.0f;
        mx  = (lane < 8) ? smx[lane]  : 0.0f;
#pragma unroll
        for (int o = 4; o > 0; o >>= 1) {
            tot += __shfl_xor_sync(0xffffffffu, tot, o);
            ws  += __shfl_xor_sync(0xffffffffu, ws,  o);
            mx   = fmaxf(mx, __shfl_xor_sync(0xffffffffu, mx, o));
        }
        if (lane == 0) {
            d_ticket = 0;                            // reset for next replay
            const float N = (float)B_ * (float)C_ * (float)HW_;
            const float weighted = (mx > 0.0f) ? (ws / mx) : 0.0f;  // BETA = 1
            out[0] = (tot + weighted) / N;
        }
    }
}

extern "C" void kernel_launch(void* const* d_in, const int* in_sizes, int n_in,
                              void* d_out, int out_size)
{
    const float* inp = (const float*)d_in[0];
    const float* tgt = (const float*)d_in[1];
    const int*   msk = (const int*)  d_in[2];
    (void)in_sizes; (void)n_in; (void)out_size;

    fused_kernel<<<dim3(64, B_), 256>>>(inp, tgt, msk, (float*)d_out);
}

// round 3
// speedup vs baseline: 2.1505x; 2.1505x over previous
#include <cuda_runtime.h>
#include <cstdint>

#define B_      16
#define C_      3
#define HW_     (512 * 512)
#define HW4_    (HW_ / 4)
#define NCLS    64
#define NSEG    (B_ * NCLS)
#define STRIDE  32              /* u64 elems -> 256 B bin stride (L2-slice spread) */
#define NBLKX   128             /* blocks per image */
#define NBLK    (NBLKX * B_)    /* 2048 */
#define THREADS 128
#define NWARP   4

// Persistent global accumulators; zeroed at load, re-zeroed by the last block
// each launch -> identical state for every graph replay.
__device__ unsigned long long d_bins[NSEG * STRIDE];
__device__ unsigned int       d_ticket;

// global packed u64: count in [44:64), sum * 2^20 in [0:44)
#define GSCALE  1048576.0f
#define GINV    (1.0f / 1048576.0f)
#define GMASK   ((1ull << 44) - 1ull)
// shared packed u32 (per lane-private slot, <=16 pixels): count in [27:32),
// sum * 2^16 in [0:27)
#define LSCALE  65536.0f
#define LINV    (1.0f / 65536.0f)
#define LCNT    (1u << 27)
#define LMASK   ((1u << 27) - 1u)

__global__ void __launch_bounds__(THREADS)
fused_kernel(const float* __restrict__ inp,
             const float* __restrict__ tgt,
             const int*   __restrict__ msk,
             float*       __restrict__ out)
{
    // lane-private histograms: bank = lane -> conflict-free RMW, no atomics
    __shared__ uint32_t hist[NWARP][NCLS][32];
    __shared__ float    s_sum[2][NCLS];
    __shared__ uint32_t s_cnt[2][NCLS];

    const int t    = threadIdx.x;
    const int wid  = t >> 5;
    const int lane = t & 31;
    const int b    = blockIdx.y;

    // zero this block's histograms (8192 u32 / 128 threads)
#pragma unroll
    for (int i = 0; i < (NWARP * NCLS * 32) / THREADS; i++)
        ((uint32_t*)hist)[i * THREADS + t] = 0u;
    __syncthreads();

    const float4* ip = (const float4*)(inp + (size_t)b * C_ * HW_);
    const float4* tp = (const float4*)(tgt + (size_t)b * C_ * HW_);
    const int4*   mp = (const int4*)  (msk + (size_t)b * HW_);
    const int vec_base = blockIdx.x * 512;   // 512 float4 (2048 px) per block

    uint32_t (*mybins)[32] = hist[wid];      // [NCLS][32]

#pragma unroll
    for (int it = 0; it < 4; it++) {
        const int v = vec_base + it * THREADS + t;

        const float4 a0 = __ldg(ip + v);
        const float4 a1 = __ldg(ip + HW4_ + v);
        const float4 a2 = __ldg(ip + 2 * HW4_ + v);
        const float4 c0 = __ldg(tp + v);
        const float4 c1 = __ldg(tp + HW4_ + v);
        const float4 c2 = __ldg(tp + 2 * HW4_ + v);
        const int4   m  = __ldg(mp + v);

        const float w0 = fabsf(a0.x - c0.x) + fabsf(a1.x - c1.x) + fabsf(a2.x - c2.x);
        const float w1 = fabsf(a0.y - c0.y) + fabsf(a1.y - c1.y) + fabsf(a2.y - c2.y);
        const float w2 = fabsf(a0.z - c0.z) + fabsf(a1.z - c1.z) + fabsf(a2.z - c2.z);
        const float w3 = fabsf(a0.w - c0.w) + fabsf(a1.w - c1.w) + fabsf(a2.w - c2.w);

        // plain LDS+IADD+STS read-modify-write; same-thread ordering guarantees
        // correctness, bank(lane) constant -> never a conflict.
        mybins[m.x & (NCLS - 1)][lane] += LCNT + __float2uint_rn(w0 * LSCALE);
        mybins[m.y & (NCLS - 1)][lane] += LCNT + __float2uint_rn(w1 * LSCALE);
        mybins[m.z & (NCLS - 1)][lane] += LCNT + __float2uint_rn(w2 * LSCALE);
        mybins[m.w & (NCLS - 1)][lane] += LCNT + __float2uint_rn(w3 * LSCALE);
    }
    __syncthreads();

    // ---- block flush: reduce hist over (warp, lane) per class ----
    {
        const int c = t & 63;       // class
        const int h = t >> 6;       // half: warps {2h, 2h+1}
        float    fs = 0.0f;
        uint32_t cc = 0u;
#pragma unroll
        for (int i = 0; i < 32; i++) {
            const int l = (i + t) & 31;              // rotated -> conflict-free
            const uint32_t p0 = hist[2 * h][c][l];
            const uint32_t p1 = hist[2 * h + 1][c][l];
            cc += (p0 >> 27) + (p1 >> 27);
            fs += (float)(p0 & LMASK) + (float)(p1 & LMASK);
        }
        s_sum[h][c] = fs;
        s_cnt[h][c] = cc;
    }
    __syncthreads();

    if (t < NCLS) {
        const float    fs = s_sum[0][t] + s_sum[1][t];   // units of 2^-16
        const uint32_t cc = s_cnt[0][t] + s_cnt[1][t];
        if (cc)
            atomicAdd(&d_bins[(size_t)(b * NCLS + t) * STRIDE],
                      ((unsigned long long)cc << 44) +
                      __float2ull_rn(fs * (LINV * GSCALE)));
    }

    // ---- last-block finalize (fused) ----
    __threadfence();
    __syncthreads();
    __shared__ unsigned int s_ticket;
    if (t == 0) s_ticket = atomicAdd(&d_ticket, 1u);
    __syncthreads();
    if (s_ticket != NBLK - 1) return;

    __threadfence();   // acquire: all blocks' REDs visible

    float tot = 0.0f, ws = 0.0f, mx = 0.0f;
#pragma unroll
    for (int k = 0; k < NSEG / THREADS; k++) {
        const int i = k * THREADS + t;
        const unsigned long long p = d_bins[(size_t)i * STRIDE];
        d_bins[(size_t)i * STRIDE] = 0ull;              // reset for next replay
        const float        s = (float)(p & GMASK) * GINV;
        const unsigned int c = (unsigned int)(p >> 44);
        const float avg = s / fmaxf((float)c * (float)C_, 1.0f);
        tot += s;
        ws  += s * avg;
        mx   = fmaxf(mx, avg);
    }

#pragma unroll
    for (int o = 16; o > 0; o >>= 1) {
        tot += __shfl_xor_sync(0xffffffffu, tot, o);
        ws  += __shfl_xor_sync(0xffffffffu, ws,  o);
        mx   = fmaxf(mx, __shfl_xor_sync(0xffffffffu, mx, o));
    }
    __shared__ float rtot[4], rws[4], rmx[4];
    if (lane == 0) { rtot[wid] = tot; rws[wid] = ws; rmx[wid] = mx; }
    __syncthreads();
    if (t == 0) {
        tot = rtot[0] + rtot[1] + rtot[2] + rtot[3];
        ws  = rws[0]  + rws[1]  + rws[2]  + rws[3];
        mx  = fmaxf(fmaxf(rmx[0], rmx[1]), fmaxf(rmx[2], rmx[3]));
        d_ticket = 0;                                   // reset for next replay
        const float N = (float)B_ * (float)C_ * (float)HW_;
        const float weighted = (mx > 0.0f) ? (ws / mx) : 0.0f;   // BETA = 1
        out[0] = (tot + weighted) / N;
    }
}

extern "C" void kernel_launch(void* const* d_in, const int* in_sizes, int n_in,
                              void* d_out, int out_size)
{
    const float* inp = (const float*)d_in[0];
    const float* tgt = (const float*)d_in[1];
    const int*   msk = (const int*)  d_in[2];
    (void)in_sizes; (void)n_in; (void)out_size;

    fused_kernel<<<dim3(NBLKX, B_), THREADS>>>(inp, tgt, msk, (float*)d_out);
}